// round 7
// baseline (speedup 1.0000x reference)
#include <cuda_runtime.h>
#include <cuda_bf16.h>

#define NN      100000
#define EE      1600000
#define IN_DIM  128
#define KD      128          // K*D
#define KH      8            // heads
#define NEG_SLOPE 0.2f

// ---------------- scratch (device globals: no allocations allowed) ----------
__device__ float g_feat_src[NN * KD];   // 51.2 MB
__device__ float g_el[NN * KH];
__device__ float g_er[NN * KH];
__device__ float g_w[EE * KH];          // 51.2 MB (unnormalized softmax numerators)
__device__ float g_s[NN * KH];          // softmax denominators

__device__ __forceinline__ void red_add_v4(float* p, float4 v) {
    asm volatile("red.global.add.v4.f32 [%0], {%1, %2, %3, %4};"
                 :: "l"(p), "f"(v.x), "f"(v.y), "f"(v.z), "f"(v.w) : "memory");
}

// ---------------------------------------------------------------------------
// K1: feat_src = feat @ W  (N x 128) plus fused el/er attention dots.
// Block: 256 threads, 32 rows per block. W (64KB) + feat tile (16KB) in smem.
// Thread (tx,ty): tx in [0,32) owns cols tx*4..tx*4+3 (float4), ty in [0,8)
// owns rows ty*4..ty*4+3 -> 4x4 register tile. FFMA-bound by design.
// ---------------------------------------------------------------------------
__global__ __launch_bounds__(256, 2)
void gemm_el_er_kernel(const float* __restrict__ feat,
                       const float* __restrict__ W,
                       const float* __restrict__ attn_l,
                       const float* __restrict__ attn_r)
{
    extern __shared__ float sm[];
    float* sW = sm;                 // 128*128
    float* sF = sm + IN_DIM * KD;   // 32*128

    const int tid = threadIdx.x;
    const int tx  = tid & 31;
    const int ty  = tid >> 5;
    const int base = blockIdx.x * 32;

    // cooperative loads (coalesced float4)
    {
        const float4* Wg = (const float4*)W;
        float4* Ws = (float4*)sW;
        #pragma unroll
        for (int i = 0; i < (IN_DIM * KD / 4) / 256; i++)
            Ws[tid + i * 256] = Wg[tid + i * 256];

        const float4* Fg = (const float4*)(feat + (long)base * IN_DIM);
        float4* Fs = (float4*)sF;
        #pragma unroll
        for (int i = 0; i < (32 * IN_DIM / 4) / 256; i++)
            Fs[tid + i * 256] = Fg[tid + i * 256];
    }
    __syncthreads();

    float4 acc[4];
    #pragma unroll
    for (int r = 0; r < 4; r++) acc[r] = make_float4(0.f, 0.f, 0.f, 0.f);

    #pragma unroll 8
    for (int i = 0; i < IN_DIM; i++) {
        float4 w4 = ((const float4*)(sW + i * KD))[tx];
        #pragma unroll
        for (int r = 0; r < 4; r++) {
            float f = sF[(ty * 4 + r) * IN_DIM + i];   // warp-uniform broadcast
            acc[r].x = fmaf(f, w4.x, acc[r].x);
            acc[r].y = fmaf(f, w4.y, acc[r].y);
            acc[r].z = fmaf(f, w4.z, acc[r].z);
            acc[r].w = fmaf(f, w4.w, acc[r].w);
        }
    }

    // epilogue: write feat_src + fused el/er
    const int h   = tx >> 2;    // head
    const int sub = tx & 3;     // quarter of the 16-wide head
    const float4 l4 = ((const float4*)attn_l)[h * 4 + sub];
    const float4 r4 = ((const float4*)attn_r)[h * 4 + sub];

    #pragma unroll
    for (int r = 0; r < 4; r++) {
        int n = base + ty * 4 + r;
        ((float4*)(g_feat_src + (long)n * KD))[tx] = acc[r];

        float pl = acc[r].x * l4.x + acc[r].y * l4.y + acc[r].z * l4.z + acc[r].w * l4.w;
        float pr = acc[r].x * r4.x + acc[r].y * r4.y + acc[r].z * r4.z + acc[r].w * r4.w;
        pl += __shfl_xor_sync(0xffffffffu, pl, 1);
        pl += __shfl_xor_sync(0xffffffffu, pl, 2);
        pr += __shfl_xor_sync(0xffffffffu, pr, 1);
        pr += __shfl_xor_sync(0xffffffffu, pr, 2);
        if (sub == 0) {
            g_el[n * KH + h] = pl;
            g_er[n * KH + h] = pr;
        }
    }
}

// ---------------------------------------------------------------------------
// K2: per edge: w = exp(leaky_relu(el[src] + er[dst])); s[dst] += w.
// (segment-max skipped: softmax is shift-invariant, values are O(1) here)
// ---------------------------------------------------------------------------
__device__ __forceinline__ float lrelu(float x) {
    return x > 0.f ? x : NEG_SLOPE * x;
}

__global__ __launch_bounds__(256)
void edge_num_kernel(const int* __restrict__ src, const int* __restrict__ dst)
{
    int e = blockIdx.x * blockDim.x + threadIdx.x;
    if (e >= EE) return;
    int s = src[e];
    int d = dst[e];

    float4 a0 = ((const float4*)(g_el + s * KH))[0];
    float4 a1 = ((const float4*)(g_el + s * KH))[1];
    float4 b0 = ((const float4*)(g_er + d * KH))[0];
    float4 b1 = ((const float4*)(g_er + d * KH))[1];

    float4 w0, w1;
    w0.x = expf(lrelu(a0.x + b0.x));
    w0.y = expf(lrelu(a0.y + b0.y));
    w0.z = expf(lrelu(a0.z + b0.z));
    w0.w = expf(lrelu(a0.w + b0.w));
    w1.x = expf(lrelu(a1.x + b1.x));
    w1.y = expf(lrelu(a1.y + b1.y));
    w1.z = expf(lrelu(a1.z + b1.z));
    w1.w = expf(lrelu(a1.w + b1.w));

    ((float4*)(g_w + (long)e * KH))[0] = w0;
    ((float4*)(g_w + (long)e * KH))[1] = w1;

    red_add_v4(g_s + d * KH,     w0);
    red_add_v4(g_s + d * KH + 4, w1);
}

// ---------------------------------------------------------------------------
// K3: one warp per edge. coeff_k = w[e,k]/s[dst,k];
// out[dst] += coeff * feat_src[src]  (128 floats, float4 per lane, red.v4)
// ---------------------------------------------------------------------------
__global__ __launch_bounds__(256)
void aggregate_kernel(const int* __restrict__ src, const int* __restrict__ dst,
                      float* __restrict__ out)
{
    int gwid = (blockIdx.x * blockDim.x + threadIdx.x) >> 5;
    int lane = threadIdx.x & 31;
    if (gwid >= EE) return;

    int s = src[gwid];
    int d = dst[gwid];

    float cc = 0.f;
    if (lane < KH)
        cc = g_w[(long)gwid * KH + lane] / g_s[d * KH + lane];
    float coeff = __shfl_sync(0xffffffffu, cc, lane >> 2);

    float4 v = ((const float4*)(g_feat_src + (long)s * KD))[lane];
    v.x *= coeff; v.y *= coeff; v.z *= coeff; v.w *= coeff;

    red_add_v4(out + (long)d * KD + lane * 4, v);
}

// ---------------------------------------------------------------------------
extern "C" void kernel_launch(void* const* d_in, const int* in_sizes, int n_in,
                              void* d_out, int out_size)
{
    const float* feat   = (const float*)d_in[0];
    const float* W      = (const float*)d_in[1];
    const float* attn_l = (const float*)d_in[2];
    const float* attn_r = (const float*)d_in[3];
    const int*   src    = (const int*)d_in[4];
    const int*   dst    = (const int*)d_in[5];
    float* out = (float*)d_out;

    // zero accumulators (capturable stream memsets)
    void* s_ptr = nullptr;
    cudaGetSymbolAddress(&s_ptr, g_s);
    cudaMemsetAsync(s_ptr, 0, (size_t)NN * KH * sizeof(float), 0);
    cudaMemsetAsync(out, 0, (size_t)out_size * sizeof(float), 0);

    // K1: GEMM + el/er
    const int smem_bytes = (IN_DIM * KD + 32 * IN_DIM) * (int)sizeof(float); // 80 KB
    cudaFuncSetAttribute(gemm_el_er_kernel,
                         cudaFuncAttributeMaxDynamicSharedMemorySize, smem_bytes);
    gemm_el_er_kernel<<<NN / 32, 256, smem_bytes>>>(feat, W, attn_l, attn_r);

    // K2: edge numerators + denominators
    edge_num_kernel<<<(EE + 255) / 256, 256>>>(src, dst);

    // K3: scatter-aggregate, one warp per edge
    aggregate_kernel<<<(EE * 32 + 255) / 256, 256>>>(src, dst, out);
}

// round 12
// speedup vs baseline: 1.9529x; 1.9529x over previous
#include <cuda_runtime.h>
#include <cuda_bf16.h>

#define NN      100000
#define EE      1600000
#define IN_DIM  128
#define KD      128          // K*D
#define KH      8            // heads
#define NEG_SLOPE 0.2f
#define NB1     98           // ceil(NN/1024) scan blocks

// ---------------- scratch (device globals: no allocations allowed) ----------
__device__ float g_feat_src[NN * KD];   // 51.2 MB
__device__ float g_el[NN * KH];
__device__ float g_er[NN * KH];

__device__ int g_deg[NN];
__device__ int g_rowtmp[NN];
__device__ int g_row[NN + 1];
__device__ int g_cursor[NN];
__device__ int g_bsum[NB1];
__device__ int g_boff[NB1];
__device__ int g_csr_src[EE];           // src ids grouped by dst

__device__ __forceinline__ float lrelu(float x) {
    return x > 0.f ? x : NEG_SLOPE * x;
}

// ---------------------------------------------------------------------------
// K1: feat_src = feat @ W (N x 128) + fused el/er attention dots.
// Measured at its scalar-FFMA floor in R7 (93us, fma=45.5% ~= rt ceiling).
// ---------------------------------------------------------------------------
__global__ __launch_bounds__(256, 2)
void gemm_el_er_kernel(const float* __restrict__ feat,
                       const float* __restrict__ W,
                       const float* __restrict__ attn_l,
                       const float* __restrict__ attn_r)
{
    extern __shared__ float sm[];
    float* sW = sm;                 // 128*128
    float* sF = sm + IN_DIM * KD;   // 32*128

    const int tid = threadIdx.x;
    const int tx  = tid & 31;
    const int ty  = tid >> 5;
    const int base = blockIdx.x * 32;

    {
        const float4* Wg = (const float4*)W;
        float4* Ws = (float4*)sW;
        #pragma unroll
        for (int i = 0; i < (IN_DIM * KD / 4) / 256; i++)
            Ws[tid + i * 256] = Wg[tid + i * 256];

        const float4* Fg = (const float4*)(feat + (long)base * IN_DIM);
        float4* Fs = (float4*)sF;
        #pragma unroll
        for (int i = 0; i < (32 * IN_DIM / 4) / 256; i++)
            Fs[tid + i * 256] = Fg[tid + i * 256];
    }
    __syncthreads();

    float4 acc[4];
    #pragma unroll
    for (int r = 0; r < 4; r++) acc[r] = make_float4(0.f, 0.f, 0.f, 0.f);

    #pragma unroll 8
    for (int i = 0; i < IN_DIM; i++) {
        float4 w4 = ((const float4*)(sW + i * KD))[tx];
        #pragma unroll
        for (int r = 0; r < 4; r++) {
            float f = sF[(ty * 4 + r) * IN_DIM + i];
            acc[r].x = fmaf(f, w4.x, acc[r].x);
            acc[r].y = fmaf(f, w4.y, acc[r].y);
            acc[r].z = fmaf(f, w4.z, acc[r].z);
            acc[r].w = fmaf(f, w4.w, acc[r].w);
        }
    }

    const int h   = tx >> 2;
    const int sub = tx & 3;
    const float4 l4 = ((const float4*)attn_l)[h * 4 + sub];
    const float4 r4 = ((const float4*)attn_r)[h * 4 + sub];

    #pragma unroll
    for (int r = 0; r < 4; r++) {
        int n = base + ty * 4 + r;
        ((float4*)(g_feat_src + (long)n * KD))[tx] = acc[r];

        float pl = acc[r].x * l4.x + acc[r].y * l4.y + acc[r].z * l4.z + acc[r].w * l4.w;
        float pr = acc[r].x * r4.x + acc[r].y * r4.y + acc[r].z * r4.z + acc[r].w * r4.w;
        pl += __shfl_xor_sync(0xffffffffu, pl, 1);
        pl += __shfl_xor_sync(0xffffffffu, pl, 2);
        pr += __shfl_xor_sync(0xffffffffu, pr, 1);
        pr += __shfl_xor_sync(0xffffffffu, pr, 2);
        if (sub == 0) {
            g_el[n * KH + h] = pl;
            g_er[n * KH + h] = pr;
        }
    }
}

// ---------------------------------------------------------------------------
// CSR build: histogram -> exclusive scan -> scatter
// ---------------------------------------------------------------------------
__global__ __launch_bounds__(256)
void count_kernel(const int* __restrict__ dst)
{
    int e = blockIdx.x * blockDim.x + threadIdx.x;
    if (e < EE) atomicAdd(&g_deg[dst[e]], 1);
}

__global__ __launch_bounds__(1024)
void scan1_kernel()
{
    __shared__ int sm[1024];
    int t = threadIdx.x;
    int i = blockIdx.x * 1024 + t;
    int v = (i < NN) ? g_deg[i] : 0;
    sm[t] = v;
    __syncthreads();
    #pragma unroll
    for (int off = 1; off < 1024; off <<= 1) {
        int x = (t >= off) ? sm[t - off] : 0;
        __syncthreads();
        sm[t] += x;
        __syncthreads();
    }
    if (t == 1023) g_bsum[blockIdx.x] = sm[1023];
    if (i < NN)    g_rowtmp[i] = sm[t] - v;   // exclusive within block
}

__global__ __launch_bounds__(128)
void scan2_kernel()
{
    __shared__ int sm[128];
    int t = threadIdx.x;
    int v = (t < NB1) ? g_bsum[t] : 0;
    sm[t] = v;
    __syncthreads();
    #pragma unroll
    for (int off = 1; off < 128; off <<= 1) {
        int x = (t >= off) ? sm[t - off] : 0;
        __syncthreads();
        sm[t] += x;
        __syncthreads();
    }
    if (t < NB1) g_boff[t] = sm[t] - v;       // exclusive across blocks
}

__global__ __launch_bounds__(256)
void scan3_kernel()
{
    int i = blockIdx.x * blockDim.x + threadIdx.x;
    if (i < NN) {
        int r = g_rowtmp[i] + g_boff[i >> 10];
        g_row[i]    = r;
        g_cursor[i] = r;
    }
    if (blockIdx.x == 0 && threadIdx.x == 0) g_row[NN] = EE;
}

__global__ __launch_bounds__(256)
void scatter_kernel(const int* __restrict__ src, const int* __restrict__ dst)
{
    int e = blockIdx.x * blockDim.x + threadIdx.x;
    if (e >= EE) return;
    int pos = atomicAdd(&g_cursor[dst[e]], 1);
    g_csr_src[pos] = src[e];
}

// ---------------------------------------------------------------------------
// Fused softmax + aggregation, one warp per dst node. Gather-only, no float
// atomics: loops this node's incoming edges, builds the per-head softmax
// denominator in registers, accumulates w * feat_src[src] in registers, and
// writes out[d] once with plain STG.128.
// Lane l owns out cols 4l..4l+3 (head = l>>2); lanes 0..7 own per-head scalars.
// ---------------------------------------------------------------------------
__global__ __launch_bounds__(256)
void agg_csr_kernel(float* __restrict__ out)
{
    int d    = (blockIdx.x * blockDim.x + threadIdx.x) >> 5;
    int lane = threadIdx.x & 31;
    if (d >= NN) return;

    const int beg = g_row[d];
    const int end = g_row[d + 1];

    float er_d = (lane < KH) ? g_er[d * KH + lane] : 0.f;
    float s_acc = 0.f;
    float4 acc = make_float4(0.f, 0.f, 0.f, 0.f);

    #pragma unroll 2
    for (int i = beg; i < end; i++) {
        int s = g_csr_src[i];               // warp-uniform broadcast load
        float w = 0.f;
        if (lane < KH) {
            float e = g_el[s * KH + lane] + er_d;
            w = expf(lrelu(e));
            s_acc += w;
        }
        float coeff = __shfl_sync(0xffffffffu, w, lane >> 2);
        float4 v = ((const float4*)(g_feat_src + (long)s * KD))[lane];
        acc.x = fmaf(coeff, v.x, acc.x);
        acc.y = fmaf(coeff, v.y, acc.y);
        acc.z = fmaf(coeff, v.z, acc.z);
        acc.w = fmaf(coeff, v.w, acc.w);
    }

    float denom = __shfl_sync(0xffffffffu, s_acc, lane >> 2);
    float inv   = (end > beg) ? 1.f / denom : 0.f;   // empty segment -> zeros
    acc.x *= inv; acc.y *= inv; acc.z *= inv; acc.w *= inv;

    ((float4*)(out + (long)d * KD))[lane] = acc;
}

// ---------------------------------------------------------------------------
extern "C" void kernel_launch(void* const* d_in, const int* in_sizes, int n_in,
                              void* d_out, int out_size)
{
    const float* feat   = (const float*)d_in[0];
    const float* W      = (const float*)d_in[1];
    const float* attn_l = (const float*)d_in[2];
    const float* attn_r = (const float*)d_in[3];
    const int*   src    = (const int*)d_in[4];
    const int*   dst    = (const int*)d_in[5];
    float* out = (float*)d_out;

    // zero the degree histogram (capturable stream memset)
    void* deg_ptr = nullptr;
    cudaGetSymbolAddress(&deg_ptr, g_deg);
    cudaMemsetAsync(deg_ptr, 0, (size_t)NN * sizeof(int), 0);

    // K1: GEMM + el/er
    const int smem_bytes = (IN_DIM * KD + 32 * IN_DIM) * (int)sizeof(float); // 80 KB
    cudaFuncSetAttribute(gemm_el_er_kernel,
                         cudaFuncAttributeMaxDynamicSharedMemorySize, smem_bytes);
    gemm_el_er_kernel<<<NN / 32, 256, smem_bytes>>>(feat, W, attn_l, attn_r);

    // CSR build (by dst)
    count_kernel<<<(EE + 255) / 256, 256>>>(dst);
    scan1_kernel<<<NB1, 1024>>>();
    scan2_kernel<<<1, 128>>>();
    scan3_kernel<<<(NN + 255) / 256, 256>>>();
    scatter_kernel<<<(EE + 255) / 256, 256>>>(src, dst);

    // fused softmax + aggregate: one warp per dst node, no float atomics
    agg_csr_kernel<<<(NN * 32 + 255) / 256, 256>>>(out);
}

// round 13
// speedup vs baseline: 2.1919x; 1.1224x over previous
#include <cuda_runtime.h>
#include <cuda_bf16.h>

#define NN      100000
#define EE      1600000
#define IN_DIM  128
#define KD      128          // K*D
#define KH      8            // heads
#define NEG_SLOPE 0.2f
#define NB1     98           // ceil(NN/1024) scan blocks

// ---------------- scratch (device globals: no allocations allowed) ----------
__device__ float g_feat_src[NN * KD];   // 51.2 MB
__device__ float g_el[NN * KH];
__device__ float g_er[NN * KH];

__device__ int g_deg[NN];
__device__ int g_rowtmp[NN];
__device__ int g_row[NN + 1];
__device__ int g_cursor[NN];
__device__ int g_bsum[NB1];
__device__ int g_boff[NB1];
__device__ int g_csr_src[EE];           // src ids grouped by dst

__device__ __forceinline__ float lrelu(float x) {
    return x > 0.f ? x : NEG_SLOPE * x;
}

// ---------------------------------------------------------------------------
// K1: feat_src = feat @ W (N x 128) + fused el/er attention dots.
// Measured at its scalar-FFMA floor (93us, fma=45.5% ~= rt ceiling).
// ---------------------------------------------------------------------------
__global__ __launch_bounds__(256, 2)
void gemm_el_er_kernel(const float* __restrict__ feat,
                       const float* __restrict__ W,
                       const float* __restrict__ attn_l,
                       const float* __restrict__ attn_r)
{
    extern __shared__ float sm[];
    float* sW = sm;                 // 128*128
    float* sF = sm + IN_DIM * KD;   // 32*128

    const int tid = threadIdx.x;
    const int tx  = tid & 31;
    const int ty  = tid >> 5;
    const int base = blockIdx.x * 32;

    {
        const float4* Wg = (const float4*)W;
        float4* Ws = (float4*)sW;
        #pragma unroll
        for (int i = 0; i < (IN_DIM * KD / 4) / 256; i++)
            Ws[tid + i * 256] = Wg[tid + i * 256];

        const float4* Fg = (const float4*)(feat + (long)base * IN_DIM);
        float4* Fs = (float4*)sF;
        #pragma unroll
        for (int i = 0; i < (32 * IN_DIM / 4) / 256; i++)
            Fs[tid + i * 256] = Fg[tid + i * 256];
    }
    __syncthreads();

    float4 acc[4];
    #pragma unroll
    for (int r = 0; r < 4; r++) acc[r] = make_float4(0.f, 0.f, 0.f, 0.f);

    #pragma unroll 8
    for (int i = 0; i < IN_DIM; i++) {
        float4 w4 = ((const float4*)(sW + i * KD))[tx];
        #pragma unroll
        for (int r = 0; r < 4; r++) {
            float f = sF[(ty * 4 + r) * IN_DIM + i];
            acc[r].x = fmaf(f, w4.x, acc[r].x);
            acc[r].y = fmaf(f, w4.y, acc[r].y);
            acc[r].z = fmaf(f, w4.z, acc[r].z);
            acc[r].w = fmaf(f, w4.w, acc[r].w);
        }
    }

    const int h   = tx >> 2;
    const int sub = tx & 3;
    const float4 l4 = ((const float4*)attn_l)[h * 4 + sub];
    const float4 r4 = ((const float4*)attn_r)[h * 4 + sub];

    #pragma unroll
    for (int r = 0; r < 4; r++) {
        int n = base + ty * 4 + r;
        ((float4*)(g_feat_src + (long)n * KD))[tx] = acc[r];

        float pl = acc[r].x * l4.x + acc[r].y * l4.y + acc[r].z * l4.z + acc[r].w * l4.w;
        float pr = acc[r].x * r4.x + acc[r].y * r4.y + acc[r].z * r4.z + acc[r].w * r4.w;
        pl += __shfl_xor_sync(0xffffffffu, pl, 1);
        pl += __shfl_xor_sync(0xffffffffu, pl, 2);
        pr += __shfl_xor_sync(0xffffffffu, pr, 1);
        pr += __shfl_xor_sync(0xffffffffu, pr, 2);
        if (sub == 0) {
            g_el[n * KH + h] = pl;
            g_er[n * KH + h] = pr;
        }
    }
}

// ---------------------------------------------------------------------------
// CSR build: histogram -> exclusive scan -> scatter  (runs on side stream,
// hidden under K1)
// ---------------------------------------------------------------------------
__global__ __launch_bounds__(256)
void count_kernel(const int* __restrict__ dst)
{
    int e = blockIdx.x * blockDim.x + threadIdx.x;
    if (e < EE) atomicAdd(&g_deg[dst[e]], 1);
}

__global__ __launch_bounds__(1024)
void scan1_kernel()
{
    __shared__ int sm[1024];
    int t = threadIdx.x;
    int i = blockIdx.x * 1024 + t;
    int v = (i < NN) ? g_deg[i] : 0;
    sm[t] = v;
    __syncthreads();
    #pragma unroll
    for (int off = 1; off < 1024; off <<= 1) {
        int x = (t >= off) ? sm[t - off] : 0;
        __syncthreads();
        sm[t] += x;
        __syncthreads();
    }
    if (t == 1023) g_bsum[blockIdx.x] = sm[1023];
    if (i < NN)    g_rowtmp[i] = sm[t] - v;   // exclusive within block
}

__global__ __launch_bounds__(128)
void scan2_kernel()
{
    __shared__ int sm[128];
    int t = threadIdx.x;
    int v = (t < NB1) ? g_bsum[t] : 0;
    sm[t] = v;
    __syncthreads();
    #pragma unroll
    for (int off = 1; off < 128; off <<= 1) {
        int x = (t >= off) ? sm[t - off] : 0;
        __syncthreads();
        sm[t] += x;
        __syncthreads();
    }
    if (t < NB1) g_boff[t] = sm[t] - v;       // exclusive across blocks
}

__global__ __launch_bounds__(256)
void scan3_kernel()
{
    int i = blockIdx.x * blockDim.x + threadIdx.x;
    if (i < NN) {
        int r = g_rowtmp[i] + g_boff[i >> 10];
        g_row[i]    = r;
        g_cursor[i] = r;
    }
    if (blockIdx.x == 0 && threadIdx.x == 0) g_row[NN] = EE;
}

__global__ __launch_bounds__(256)
void scatter_kernel(const int* __restrict__ src, const int* __restrict__ dst)
{
    int e = blockIdx.x * blockDim.x + threadIdx.x;
    if (e >= EE) return;
    int pos = atomicAdd(&g_cursor[dst[e]], 1);
    g_csr_src[pos] = src[e];
}

// ---------------------------------------------------------------------------
// Fused softmax + aggregation, one warp per dst node. Gather-only, no float
// atomics. 2-edge software pipeline for extra memory-level parallelism.
// Lane l owns out cols 4l..4l+3 (head = l>>2); lanes 0..7 own per-head scalars.
// ---------------------------------------------------------------------------
__global__ __launch_bounds__(256)
void agg_csr_kernel(float* __restrict__ out)
{
    int d    = (blockIdx.x * blockDim.x + threadIdx.x) >> 5;
    int lane = threadIdx.x & 31;
    if (d >= NN) return;

    const int beg = g_row[d];
    const int end = g_row[d + 1];

    float er_d = (lane < KH) ? g_er[d * KH + lane] : 0.f;
    float s_acc = 0.f;
    float4 acc = make_float4(0.f, 0.f, 0.f, 0.f);

    int i = beg;
    for (; i + 2 <= end; i += 2) {
        int s0 = g_csr_src[i];
        int s1 = g_csr_src[i + 1];
        // issue both gathers up front (independent -> MLP)
        float4 v0 = ((const float4*)(g_feat_src + (long)s0 * KD))[lane];
        float4 v1 = ((const float4*)(g_feat_src + (long)s1 * KD))[lane];
        float w0 = 0.f, w1 = 0.f;
        if (lane < KH) {
            w0 = expf(lrelu(g_el[s0 * KH + lane] + er_d));
            w1 = expf(lrelu(g_el[s1 * KH + lane] + er_d));
            s_acc += w0 + w1;
        }
        float c0 = __shfl_sync(0xffffffffu, w0, lane >> 2);
        float c1 = __shfl_sync(0xffffffffu, w1, lane >> 2);
        acc.x = fmaf(c0, v0.x, acc.x);
        acc.y = fmaf(c0, v0.y, acc.y);
        acc.z = fmaf(c0, v0.z, acc.z);
        acc.w = fmaf(c0, v0.w, acc.w);
        acc.x = fmaf(c1, v1.x, acc.x);
        acc.y = fmaf(c1, v1.y, acc.y);
        acc.z = fmaf(c1, v1.z, acc.z);
        acc.w = fmaf(c1, v1.w, acc.w);
    }
    if (i < end) {
        int s = g_csr_src[i];
        float4 v = ((const float4*)(g_feat_src + (long)s * KD))[lane];
        float w = 0.f;
        if (lane < KH) {
            w = expf(lrelu(g_el[s * KH + lane] + er_d));
            s_acc += w;
        }
        float c = __shfl_sync(0xffffffffu, w, lane >> 2);
        acc.x = fmaf(c, v.x, acc.x);
        acc.y = fmaf(c, v.y, acc.y);
        acc.z = fmaf(c, v.z, acc.z);
        acc.w = fmaf(c, v.w, acc.w);
    }

    float denom = __shfl_sync(0xffffffffu, s_acc, lane >> 2);
    float inv   = (end > beg) ? 1.f / denom : 0.f;   // empty segment -> zeros
    acc.x *= inv; acc.y *= inv; acc.z *= inv; acc.w *= inv;

    ((float4*)(out + (long)d * KD))[lane] = acc;
}

// ---------------------------------------------------------------------------
extern "C" void kernel_launch(void* const* d_in, const int* in_sizes, int n_in,
                              void* d_out, int out_size)
{
    const float* feat   = (const float*)d_in[0];
    const float* W      = (const float*)d_in[1];
    const float* attn_l = (const float*)d_in[2];
    const float* attn_r = (const float*)d_in[3];
    const int*   src    = (const int*)d_in[4];
    const int*   dst    = (const int*)d_in[5];
    float* out = (float*)d_out;

    // Lazily created host-side objects (first call is the uncaptured
    // correctness run). No device memory involved; identical work every call.
    static cudaStream_t s2 = nullptr;
    static cudaEvent_t  ev_fork = nullptr, ev_join = nullptr;
    if (s2 == nullptr) {
        cudaStreamCreateWithFlags(&s2, cudaStreamNonBlocking);
        cudaEventCreateWithFlags(&ev_fork, cudaEventDisableTiming);
        cudaEventCreateWithFlags(&ev_join, cudaEventDisableTiming);
    }

    static void* deg_ptr = nullptr;
    if (deg_ptr == nullptr) cudaGetSymbolAddress(&deg_ptr, g_deg);

    // ---- fork: CSR build on s2, GEMM on capture stream (independent) ----
    cudaEventRecord(ev_fork, 0);
    cudaStreamWaitEvent(s2, ev_fork, 0);

    // branch B (s2): CSR build by dst
    cudaMemsetAsync(deg_ptr, 0, (size_t)NN * sizeof(int), s2);
    count_kernel<<<(EE + 255) / 256, 256, 0, s2>>>(dst);
    scan1_kernel<<<NB1, 1024, 0, s2>>>();
    scan2_kernel<<<1, 128, 0, s2>>>();
    scan3_kernel<<<(NN + 255) / 256, 256, 0, s2>>>();
    scatter_kernel<<<(EE + 255) / 256, 256, 0, s2>>>(src, dst);
    cudaEventRecord(ev_join, s2);

    // branch A (capture stream): K1 GEMM + el/er
    const int smem_bytes = (IN_DIM * KD + 32 * IN_DIM) * (int)sizeof(float); // 80 KB
    cudaFuncSetAttribute(gemm_el_er_kernel,
                         cudaFuncAttributeMaxDynamicSharedMemorySize, smem_bytes);
    gemm_el_er_kernel<<<NN / 32, 256, smem_bytes>>>(feat, W, attn_l, attn_r);

    // ---- join, then fused softmax + aggregate ----
    cudaStreamWaitEvent(0, ev_join, 0);
    agg_csr_kernel<<<(NN * 32 + 255) / 256, 256>>>(out);
}